// round 7
// baseline (speedup 1.0000x reference)
#include <cuda_runtime.h>
#include <cuda_fp16.h>
#include <cstdint>
#include <math.h>

// ---------------- problem constants ----------------
#define S_LEN 2048
#define HID   4096
#define NH    32
#define NKV   8
#define HD    128
#define QS    (NH * HD)          // 4096
#define KVS   (NKV * HD)         // 1024
#define QKV_N (QS + 2 * KVS)     // 6144
#define SCALE 0.08838834764831845f  // 128^-0.5

// ---------------- scratch (static device globals; no allocs) ----------------
__device__ float g_qkv[S_LEN * QKV_N];       // QKV projection output [S, 6144]
__device__ float g_q[NH * S_LEN * HD];       // RoPE'd Q, head-major [h][s][d]
__device__ float g_k[NKV * S_LEN * HD];      // RoPE'd K, head-major
__device__ float g_v[NKV * S_LEN * HD];      // V, head-major
__device__ float g_attn[S_LEN * QS];         // attention output [s][h*128+d]

// fp16 split operands for tensor-core GEMMs
__device__ __half g_ah[S_LEN * HID];         // activation hi  [M,K]
__device__ __half g_al[S_LEN * HID];         // activation lo
__device__ __half g_wqh[QKV_N * HID];        // w_qkv^T hi [N,K]
__device__ __half g_wql[QKV_N * HID];        // w_qkv^T lo
__device__ __half g_woh[HID * QS];           // w_o^T hi   [N,K]
__device__ __half g_wol[HID * QS];           // w_o^T lo

// ==========================================================================
// small PTX helpers
// ==========================================================================
__device__ __forceinline__ uint32_t smem_to_u32(const void* p) {
    uint32_t a;
    asm("{ .reg .u64 t; cvta.to.shared.u64 t, %1; cvt.u32.u64 %0, t; }"
        : "=r"(a) : "l"(p));
    return a;
}
__device__ __forceinline__ void cp_async16(uint32_t dst, const void* src) {
    asm volatile("cp.async.cg.shared.global [%0], [%1], 16;"
                 :: "r"(dst), "l"(src) : "memory");
}
#define CP_COMMIT() asm volatile("cp.async.commit_group;" ::: "memory")
#define CP_WAIT(n)  asm volatile("cp.async.wait_group %0;" :: "n"(n) : "memory")

__device__ __forceinline__ void ldsm_x4(uint32_t* r, uint32_t addr) {
    asm volatile("ldmatrix.sync.aligned.m8n8.x4.shared.b16 {%0,%1,%2,%3}, [%4];"
                 : "=r"(r[0]), "=r"(r[1]), "=r"(r[2]), "=r"(r[3]) : "r"(addr));
}
__device__ __forceinline__ void ldsm_x2(uint32_t* r, uint32_t addr) {
    asm volatile("ldmatrix.sync.aligned.m8n8.x2.shared.b16 {%0,%1}, [%2];"
                 : "=r"(r[0]), "=r"(r[1]) : "r"(addr));
}
__device__ __forceinline__ void mma16816(float* c, const uint32_t* a, const uint32_t* b) {
    asm volatile("mma.sync.aligned.m16n8k16.row.col.f32.f16.f16.f32 "
                 "{%0,%1,%2,%3}, {%4,%5,%6,%7}, {%8,%9}, {%0,%1,%2,%3};"
                 : "+f"(c[0]), "+f"(c[1]), "+f"(c[2]), "+f"(c[3])
                 : "r"(a[0]), "r"(a[1]), "r"(a[2]), "r"(a[3]),
                   "r"(b[0]), "r"(b[1]));
}

// ==========================================================================
// split-fp16 HMMA GEMM: C[M,N] = (Ah+Al)[M,K] @ (Bh+Bl)[N,K]^T
// CTA tile 128x128, BK=32, 256 threads (8 warps, 2x4), warp tile 64x32.
// Tiles in smem: 128 rows x 32 fp16, row stride 80B (conflict-free ldmatrix).
// cp.async double buffer.
// ==========================================================================
#define ROW_B   80                    // padded row stride bytes (32 fp16 = 64B + 16)
#define TILE_B  (128 * ROW_B)         // 10240
#define STAGE_B (4 * TILE_B)          // 40960 (Ah, Al, Bh, Bl)
#define GEMM_SMEM (2 * STAGE_B)       // 81920

__global__ __launch_bounds__(256) void gemm_hmma_split(
    const __half* __restrict__ Ah, const __half* __restrict__ Al,
    const __half* __restrict__ Bh, const __half* __restrict__ Bl,
    float* __restrict__ C, int Nglob, int Kglob)
{
    extern __shared__ __align__(128) char smem[];
    const uint32_t sbase = smem_to_u32(smem);
    const int tid  = threadIdx.x;
    const int wid  = tid >> 5;
    const int lane = tid & 31;
    const int brow = blockIdx.y * 128;
    const int bcol = blockIdx.x * 128;
    const int NC   = Kglob / 32;

    const int wm = (wid >> 2) * 64;      // warp row offset within CTA tile
    const int wn = (wid & 3) * 32;       // warp col offset

    const __half* __restrict__ srcs[4] = { Ah, Al, Bh, Bl };

    // accumulators: 4 m-tiles x 4 n-tiles x 4 floats
    float acc[4][4][4];
#pragma unroll
    for (int i = 0; i < 4; i++)
#pragma unroll
        for (int j = 0; j < 4; j++)
#pragma unroll
            for (int e = 0; e < 4; e++) acc[i][j][e] = 0.0f;

    // ------- stage loader: 4 tiles x 512 x 16B chunks, 2048 chunks / 256 thr = 8 each
    auto load_stage = [&](int s, int c) {
        const int k0 = c * 32;
        const uint32_t stage = sbase + s * STAGE_B;
#pragma unroll
        for (int m = 0; m < 4; m++) {
            const int rowbase = (m < 2) ? brow : bcol;
            const __half* src = srcs[m];
            // 512 chunks: thread handles 2 (tid and tid+256)
#pragma unroll
            for (int t = 0; t < 2; t++) {
                int e  = tid + t * 256;       // 0..511
                int r  = e >> 2;              // row 0..127
                int cc = e & 3;               // 16B chunk within row
                const void* g = src + (size_t)(rowbase + r) * Kglob + k0 + cc * 8;
                cp_async16(stage + m * TILE_B + r * ROW_B + cc * 16, g);
            }
        }
    };

    load_stage(0, 0);
    CP_COMMIT();

    for (int c = 0; c < NC; c++) {
        if (c + 1 < NC) { load_stage((c + 1) & 1, c + 1); CP_COMMIT(); CP_WAIT(1); }
        else            { CP_WAIT(0); }
        __syncthreads();

        const uint32_t st = sbase + (c & 1) * STAGE_B;
        const uint32_t a_base = st;                       // Ah
        const uint32_t b_base = st + 2 * TILE_B;          // Bh

        // per-lane ldmatrix addresses (row part)
        const int arow = wm + (lane & 15);                // + i*16
        const int acol16 = (lane >> 4) * 16;              // 16B k-half select
        const int brow8 = wn + (lane & 7);                // + j*8
        const int bcol16 = ((lane >> 3) & 1) * 16;

#pragma unroll
        for (int ks = 0; ks < 2; ks++) {                  // two k16 steps per BK=32
            const int koff = ks * 32;                     // 16 fp16 = 32B
            uint32_t ahf[4][4], alf[4][4], bhf[4][2], blf[4][2];
#pragma unroll
            for (int i = 0; i < 4; i++) {
                uint32_t addr = a_base + (arow + i * 16) * ROW_B + acol16 + koff;
                ldsm_x4(ahf[i], addr);
                ldsm_x4(alf[i], addr + TILE_B);
            }
#pragma unroll
            for (int j = 0; j < 4; j++) {
                uint32_t addr = b_base + (brow8 + j * 8) * ROW_B + bcol16 + koff;
                ldsm_x2(bhf[j], addr);
                ldsm_x2(blf[j], addr + TILE_B);
            }
#pragma unroll
            for (int i = 0; i < 4; i++)
#pragma unroll
                for (int j = 0; j < 4; j++) {
                    mma16816(acc[i][j], ahf[i], bhf[j]);
                    mma16816(acc[i][j], ahf[i], blf[j]);
                    mma16816(acc[i][j], alf[i], bhf[j]);
                }
        }
        __syncthreads();
    }

    // ------- epilogue: c0,c1 -> (row, col..col+1); c2,c3 -> (row+8, ...)
    const int erow = brow + wm + (lane >> 2);
    const int ecol = bcol + wn + (lane & 3) * 2;
#pragma unroll
    for (int i = 0; i < 4; i++) {
#pragma unroll
        for (int j = 0; j < 4; j++) {
            float* p0 = C + (size_t)(erow + i * 16) * Nglob + ecol + j * 8;
            float* p1 = C + (size_t)(erow + i * 16 + 8) * Nglob + ecol + j * 8;
            *(float2*)p0 = make_float2(acc[i][j][0], acc[i][j][1]);
            *(float2*)p1 = make_float2(acc[i][j][2], acc[i][j][3]);
        }
    }
}

// ==========================================================================
// fp32 -> fp16 hi/lo split (row-major, same layout)
// ==========================================================================
__global__ __launch_bounds__(256) void convert_split(
    const float* __restrict__ x, __half* __restrict__ hi,
    __half* __restrict__ lo, int n4)
{
    int i = blockIdx.x * 256 + threadIdx.x;
    if (i >= n4) return;
    float4 v = ((const float4*)x)[i];
    float vals[4] = {v.x, v.y, v.z, v.w};
    __half hs[4], ls[4];
#pragma unroll
    for (int j = 0; j < 4; j++) {
        __half h = __float2half_rn(vals[j]);
        hs[j] = h;
        ls[j] = __float2half_rn(vals[j] - __half2float(h));
    }
    *(uint2*)(hi + i * 4) = *(uint2*)hs;
    *(uint2*)(lo + i * 4) = *(uint2*)ls;
}

// ==========================================================================
// W[K,N] fp32 -> W^T[N,K] fp16 hi/lo (32x32 tiled transpose)
// ==========================================================================
__global__ __launch_bounds__(256) void transpose_split(
    const float* __restrict__ W, __half* __restrict__ th,
    __half* __restrict__ tl, int K, int N)
{
    __shared__ float t[32][33];
    const int bx = blockIdx.x * 32;   // N offset
    const int by = blockIdx.y * 32;   // K offset
    const int tx = threadIdx.x;       // 0..31
    const int ty = threadIdx.y;       // 0..7
#pragma unroll
    for (int i = 0; i < 32; i += 8)
        t[ty + i][tx] = W[(size_t)(by + ty + i) * N + bx + tx];
    __syncthreads();
#pragma unroll
    for (int i = 0; i < 32; i += 8) {
        float v = t[tx][ty + i];
        __half h = __float2half_rn(v);
        size_t o = (size_t)(bx + ty + i) * K + by + tx;
        th[o] = h;
        tl[o] = __float2half_rn(v - __half2float(h));
    }
}

// ==========================================================================
// RoPE + split: g_qkv[s] -> g_q / g_k (NeoX rope) / g_v (copy), head-major.
// ==========================================================================
__global__ __launch_bounds__(256) void rope_split_kernel(const int* __restrict__ positions)
{
    const int s   = blockIdx.x;
    const int tid = threadIdx.x;
    __shared__ float cs[64], sn[64];

    if (tid < 64) {
        float inv_freq = powf(10000.0f, -((float)(2 * tid)) / 128.0f);
        float ang = (float)positions[s] * inv_freq;
        cs[tid] = cosf(ang);
        sn[tid] = sinf(ang);
    }
    __syncthreads();

    const float* row = g_qkv + (size_t)s * QKV_N;

    for (int idx = tid; idx < NH * 64; idx += 256) {
        int h = idx >> 6, d = idx & 63;
        float x1 = row[h * HD + d];
        float x2 = row[h * HD + d + 64];
        float* q = g_q + ((size_t)h * S_LEN + s) * HD;
        q[d]      = x1 * cs[d] - x2 * sn[d];
        q[d + 64] = x2 * cs[d] + x1 * sn[d];
    }
    for (int idx = tid; idx < NKV * 64; idx += 256) {
        int h = idx >> 6, d = idx & 63;
        const float* kr = row + QS;
        float x1 = kr[h * HD + d];
        float x2 = kr[h * HD + d + 64];
        float* k = g_k + ((size_t)h * S_LEN + s) * HD;
        k[d]      = x1 * cs[d] - x2 * sn[d];
        k[d + 64] = x2 * cs[d] + x1 * sn[d];
    }
    for (int idx = tid; idx < NKV * HD; idx += 256) {
        int h = idx >> 7, d = idx & 127;
        g_v[((size_t)h * S_LEN + s) * HD + d] = row[QS + KVS + h * HD + d];
    }
}

// ==========================================================================
// Flash attention, fp32, causal. Br=Bc=64, 256 threads.
// ==========================================================================
#define BR 64
#define BC 64
#define QK_STRIDE (BR + 4)
#define V_STRIDE  (HD + 4)
#define FLASH_SMEM_FLOATS (HD * QK_STRIDE + HD * QK_STRIDE \
                         + BC * V_STRIDE + BR * QK_STRIDE)

__global__ __launch_bounds__(256) void flash_attn_kernel()
{
    extern __shared__ float fsmem[];
    float* Qst = fsmem;
    float* Kst = Qst + HD * QK_STRIDE;
    float* Vs  = Kst + HD * QK_STRIDE;
    float* Ps  = Vs  + BC * V_STRIDE;

    const int qt  = blockIdx.x;
    const int h   = blockIdx.y;
    const int kvh = h >> 2;
    const int tid = threadIdx.x;
    const int ty  = tid >> 4;
    const int tx  = tid & 15;
    const int qbase = qt * BR;

    {
        const float* Qg = g_q + ((size_t)h * S_LEN + qbase) * HD;
        int r = tid & 63;
        int d0 = (tid >> 6) << 2;
#pragma unroll
        for (int i = 0; i < 8; i++) {
            int d = d0 + i * 16;
            float4 v = *(const float4*)(Qg + r * HD + d);
            Qst[(d + 0) * QK_STRIDE + r] = v.x;
            Qst[(d + 1) * QK_STRIDE + r] = v.y;
            Qst[(d + 2) * QK_STRIDE + r] = v.z;
            Qst[(d + 3) * QK_STRIDE + r] = v.w;
        }
    }

    float Ofrag[4][8];
    float m_i[4], l_i[4];
#pragma unroll
    for (int i = 0; i < 4; i++) {
        m_i[i] = -1e30f;
        l_i[i] = 0.0f;
#pragma unroll
        for (int j = 0; j < 8; j++) Ofrag[i][j] = 0.0f;
    }

    for (int jt = 0; jt <= qt; jt++) {
        const int kbase = jt * BC;
        {
            const float* Kg = g_k + ((size_t)kvh * S_LEN + kbase) * HD;
            const float* Vg = g_v + ((size_t)kvh * S_LEN + kbase) * HD;
            int c = tid & 63;
            int d0 = (tid >> 6) << 2;
#pragma unroll
            for (int i = 0; i < 8; i++) {
                int d = d0 + i * 16;
                float4 kv = *(const float4*)(Kg + c * HD + d);
                Kst[(d + 0) * QK_STRIDE + c] = kv.x;
                Kst[(d + 1) * QK_STRIDE + c] = kv.y;
                Kst[(d + 2) * QK_STRIDE + c] = kv.z;
                Kst[(d + 3) * QK_STRIDE + c] = kv.w;
                float4 vv = *(const float4*)(Vg + c * HD + d);
                *(float4*)&Vs[c * V_STRIDE + d] = vv;
            }
        }
        __syncthreads();

        float sfrag[4][4];
#pragma unroll
        for (int i = 0; i < 4; i++)
#pragma unroll
            for (int j = 0; j < 4; j++) sfrag[i][j] = 0.0f;

#pragma unroll 4
        for (int kk = 0; kk < HD; kk++) {
            float4 a = *(float4*)&Qst[kk * QK_STRIDE + ty * 4];
            float4 b = *(float4*)&Kst[kk * QK_STRIDE + tx * 4];
            float ar[4] = {a.x, a.y, a.z, a.w};
            float br[4] = {b.x, b.y, b.z, b.w};
#pragma unroll
            for (int i = 0; i < 4; i++)
#pragma unroll
                for (int j = 0; j < 4; j++)
                    sfrag[i][j] = fmaf(ar[i], br[j], sfrag[i][j]);
        }

        if (jt == qt) {
#pragma unroll
            for (int i = 0; i < 4; i++)
#pragma unroll
                for (int j = 0; j < 4; j++) {
                    float sv = sfrag[i][j] * SCALE;
                    sfrag[i][j] = (tx * 4 + j > ty * 4 + i) ? -1e30f : sv;
                }
        } else {
#pragma unroll
            for (int i = 0; i < 4; i++)
#pragma unroll
                for (int j = 0; j < 4; j++) sfrag[i][j] *= SCALE;
        }

#pragma unroll
        for (int i = 0; i < 4; i++) {
            float mloc = fmaxf(fmaxf(sfrag[i][0], sfrag[i][1]),
                               fmaxf(sfrag[i][2], sfrag[i][3]));
#pragma unroll
            for (int off = 8; off > 0; off >>= 1)
                mloc = fmaxf(mloc, __shfl_xor_sync(0xffffffffu, mloc, off, 16));

            float mnew  = fmaxf(m_i[i], mloc);
            float alpha = __expf(m_i[i] - mnew);
            float rsum = 0.0f;
            float p[4];
#pragma unroll
            for (int j = 0; j < 4; j++) {
                p[j] = __expf(sfrag[i][j] - mnew);
                rsum += p[j];
            }
            *(float4*)&Ps[(ty * 4 + i) * QK_STRIDE + tx * 4] =
                make_float4(p[0], p[1], p[2], p[3]);
#pragma unroll
            for (int off = 8; off > 0; off >>= 1)
                rsum += __shfl_xor_sync(0xffffffffu, rsum, off, 16);

            l_i[i] = l_i[i] * alpha + rsum;
            m_i[i] = mnew;
#pragma unroll
            for (int j = 0; j < 8; j++) Ofrag[i][j] *= alpha;
        }
        __syncthreads();

#pragma unroll 4
        for (int c = 0; c < BC; c++) {
            float4 v0 = *(float4*)&Vs[c * V_STRIDE + tx * 8];
            float4 v1 = *(float4*)&Vs[c * V_STRIDE + tx * 8 + 4];
            float vv[8] = {v0.x, v0.y, v0.z, v0.w, v1.x, v1.y, v1.z, v1.w};
#pragma unroll
            for (int i = 0; i < 4; i++) {
                float pv = Ps[(ty * 4 + i) * QK_STRIDE + c];
#pragma unroll
                for (int j = 0; j < 8; j++)
                    Ofrag[i][j] = fmaf(pv, vv[j], Ofrag[i][j]);
            }
        }
        __syncthreads();
    }

#pragma unroll
    for (int i = 0; i < 4; i++) {
        float inv_l = 1.0f / l_i[i];
        float* orow = g_attn + (size_t)(qbase + ty * 4 + i) * QS + h * HD + tx * 8;
        *(float4*)(orow) = make_float4(Ofrag[i][0] * inv_l, Ofrag[i][1] * inv_l,
                                       Ofrag[i][2] * inv_l, Ofrag[i][3] * inv_l);
        *(float4*)(orow + 4) = make_float4(Ofrag[i][4] * inv_l, Ofrag[i][5] * inv_l,
                                           Ofrag[i][6] * inv_l, Ofrag[i][7] * inv_l);
    }
}

// ==========================================================================
// launch
// ==========================================================================
extern "C" void kernel_launch(void* const* d_in, const int* in_sizes, int n_in,
                              void* d_out, int out_size)
{
    const int*   positions = (const int*)d_in[0];
    const float* hidden    = (const float*)d_in[1];
    const float* w_qkv     = (const float*)d_in[2];
    const float* w_o       = (const float*)d_in[3];
    float*       out       = (float*)d_out;

    void *p_qkv, *p_attn, *p_ah, *p_al, *p_wqh, *p_wql, *p_woh, *p_wol;
    cudaGetSymbolAddress(&p_qkv,  g_qkv);
    cudaGetSymbolAddress(&p_attn, g_attn);
    cudaGetSymbolAddress(&p_ah,   g_ah);
    cudaGetSymbolAddress(&p_al,   g_al);
    cudaGetSymbolAddress(&p_wqh,  g_wqh);
    cudaGetSymbolAddress(&p_wql,  g_wql);
    cudaGetSymbolAddress(&p_woh,  g_woh);
    cudaGetSymbolAddress(&p_wol,  g_wol);
    float* qkv  = (float*)p_qkv;
    float* attn = (float*)p_attn;
    __half* ah  = (__half*)p_ah;
    __half* al  = (__half*)p_al;
    __half* wqh = (__half*)p_wqh;
    __half* wql = (__half*)p_wql;
    __half* woh = (__half*)p_woh;
    __half* wol = (__half*)p_wol;

    const int flash_smem = FLASH_SMEM_FLOATS * (int)sizeof(float);
    cudaFuncSetAttribute(flash_attn_kernel,
                         cudaFuncAttributeMaxDynamicSharedMemorySize, flash_smem);
    cudaFuncSetAttribute(gemm_hmma_split,
                         cudaFuncAttributeMaxDynamicSharedMemorySize, GEMM_SMEM);

    // 1) operand prep for QKV GEMM
    {
        int n4 = (S_LEN * HID) / 4;
        convert_split<<<(n4 + 255) / 256, 256>>>(hidden, ah, al, n4);
        dim3 tg(QKV_N / 32, HID / 32);
        transpose_split<<<tg, dim3(32, 8)>>>(w_qkv, wqh, wql, HID, QKV_N);
    }
    // 2) QKV projection: [2048,4096] @ [4096,6144] via HMMA split-fp16
    {
        dim3 grid(QKV_N / 128, S_LEN / 128);
        gemm_hmma_split<<<grid, 256, GEMM_SMEM>>>(ah, al, wqh, wql, qkv, QKV_N, HID);
    }
    // 3) RoPE + head-major split
    rope_split_kernel<<<S_LEN, 256>>>(positions);
    // 4) causal GQA flash attention (fp32)
    {
        dim3 grid(S_LEN / BR, NH);
        flash_attn_kernel<<<grid, 256, flash_smem>>>();
    }
    // 5) operand prep for O GEMM
    {
        int n4 = (S_LEN * QS) / 4;
        convert_split<<<(n4 + 255) / 256, 256>>>(attn, ah, al, n4);
        dim3 tg(HID / 32, QS / 32);
        transpose_split<<<tg, dim3(32, 8)>>>(w_o, woh, wol, QS, HID);
    }
    // 6) output projection: [2048,4096] @ [4096,4096] via HMMA split-fp16
    {
        dim3 grid(HID / 128, S_LEN / 128);
        gemm_hmma_split<<<grid, 256, GEMM_SMEM>>>(ah, al, woh, wol, out, HID, QS);
    }
}

// round 8
// speedup vs baseline: 1.0004x; 1.0004x over previous
#include <cuda_runtime.h>
#include <cuda_fp16.h>
#include <cstdint>
#include <math.h>

// ---------------- problem constants ----------------
#define S_LEN 2048
#define HID   4096
#define NH    32
#define NKV   8
#define HD    128
#define QS    (NH * HD)          // 4096
#define KVS   (NKV * HD)         // 1024
#define QKV_N (QS + 2 * KVS)     // 6144
#define SCALE 0.08838834764831845f  // 128^-0.5

// ---------------- scratch (static device globals; no allocs) ----------------
__device__ float g_qkv[S_LEN * QKV_N];       // QKV projection output [S, 6144]
__device__ float g_q[NH * S_LEN * HD];       // RoPE'd Q, head-major [h][s][d]
__device__ float g_k[NKV * S_LEN * HD];      // RoPE'd K, head-major
__device__ float g_v[NKV * S_LEN * HD];      // V, head-major
__device__ float g_attn[S_LEN * QS];         // attention output [s][h*128+d]

// fp16 split operands for tensor-core GEMMs
__device__ __half g_ah[S_LEN * HID];         // activation hi  [M,K]
__device__ __half g_al[S_LEN * HID];         // activation lo
__device__ __half g_wqh[QKV_N * HID];        // w_qkv^T hi [N,K]
__device__ __half g_wql[QKV_N * HID];        // w_qkv^T lo
__device__ __half g_woh[HID * QS];           // w_o^T hi   [N,K]
__device__ __half g_wol[HID * QS];           // w_o^T lo

// ==========================================================================
// small PTX helpers
// ==========================================================================
__device__ __forceinline__ uint32_t smem_to_u32(const void* p) {
    uint32_t a;
    asm("{ .reg .u64 t; cvta.to.shared.u64 t, %1; cvt.u32.u64 %0, t; }"
        : "=r"(a) : "l"(p));
    return a;
}
__device__ __forceinline__ void cp_async16(uint32_t dst, const void* src) {
    asm volatile("cp.async.cg.shared.global [%0], [%1], 16;"
                 :: "r"(dst), "l"(src) : "memory");
}
#define CP_COMMIT() asm volatile("cp.async.commit_group;" ::: "memory")
#define CP_WAIT(n)  asm volatile("cp.async.wait_group %0;" :: "n"(n) : "memory")

__device__ __forceinline__ void ldsm_x4(uint32_t* r, uint32_t addr) {
    asm volatile("ldmatrix.sync.aligned.m8n8.x4.shared.b16 {%0,%1,%2,%3}, [%4];"
                 : "=r"(r[0]), "=r"(r[1]), "=r"(r[2]), "=r"(r[3]) : "r"(addr));
}
__device__ __forceinline__ void ldsm_x2(uint32_t* r, uint32_t addr) {
    asm volatile("ldmatrix.sync.aligned.m8n8.x2.shared.b16 {%0,%1}, [%2];"
                 : "=r"(r[0]), "=r"(r[1]) : "r"(addr));
}
__device__ __forceinline__ void mma16816(float* c, const uint32_t* a, const uint32_t* b) {
    asm volatile("mma.sync.aligned.m16n8k16.row.col.f32.f16.f16.f32 "
                 "{%0,%1,%2,%3}, {%4,%5,%6,%7}, {%8,%9}, {%0,%1,%2,%3};"
                 : "+f"(c[0]), "+f"(c[1]), "+f"(c[2]), "+f"(c[3])
                 : "r"(a[0]), "r"(a[1]), "r"(a[2]), "r"(a[3]),
                   "r"(b[0]), "r"(b[1]));
}

// ==========================================================================
// split-fp16 HMMA GEMM: C[M,N] = (Ah+Al)[M,K] @ (Bh+Bl)[N,K]^T
// CTA tile 128x128, BK=32, 256 threads (8 warps, 2x4), warp tile 64x32.
// Tiles in smem: 128 rows x 32 fp16, row stride 80B (conflict-free ldmatrix).
// cp.async double buffer.
// ==========================================================================
#define ROW_B   80                    // padded row stride bytes (32 fp16 = 64B + 16)
#define TILE_B  (128 * ROW_B)         // 10240
#define STAGE_B (4 * TILE_B)          // 40960 (Ah, Al, Bh, Bl)
#define GEMM_SMEM (2 * STAGE_B)       // 81920

__global__ __launch_bounds__(256) void gemm_hmma_split(
    const __half* __restrict__ Ah, const __half* __restrict__ Al,
    const __half* __restrict__ Bh, const __half* __restrict__ Bl,
    float* __restrict__ C, int Nglob, int Kglob)
{
    extern __shared__ __align__(128) char smem[];
    const uint32_t sbase = smem_to_u32(smem);
    const int tid  = threadIdx.x;
    const int wid  = tid >> 5;
    const int lane = tid & 31;
    const int brow = blockIdx.y * 128;
    const int bcol = blockIdx.x * 128;
    const int NC   = Kglob / 32;

    const int wm = (wid >> 2) * 64;      // warp row offset within CTA tile
    const int wn = (wid & 3) * 32;       // warp col offset

    const __half* __restrict__ srcs[4] = { Ah, Al, Bh, Bl };

    // accumulators: 4 m-tiles x 4 n-tiles x 4 floats
    float acc[4][4][4];
#pragma unroll
    for (int i = 0; i < 4; i++)
#pragma unroll
        for (int j = 0; j < 4; j++)
#pragma unroll
            for (int e = 0; e < 4; e++) acc[i][j][e] = 0.0f;

    // ------- stage loader: 4 tiles x 512 x 16B chunks, 2048 chunks / 256 thr = 8 each
    auto load_stage = [&](int s, int c) {
        const int k0 = c * 32;
        const uint32_t stage = sbase + s * STAGE_B;
#pragma unroll
        for (int m = 0; m < 4; m++) {
            const int rowbase = (m < 2) ? brow : bcol;
            const __half* src = srcs[m];
            // 512 chunks: thread handles 2 (tid and tid+256)
#pragma unroll
            for (int t = 0; t < 2; t++) {
                int e  = tid + t * 256;       // 0..511
                int r  = e >> 2;              // row 0..127
                int cc = e & 3;               // 16B chunk within row
                const void* g = src + (size_t)(rowbase + r) * Kglob + k0 + cc * 8;
                cp_async16(stage + m * TILE_B + r * ROW_B + cc * 16, g);
            }
        }
    };

    load_stage(0, 0);
    CP_COMMIT();

    for (int c = 0; c < NC; c++) {
        if (c + 1 < NC) { load_stage((c + 1) & 1, c + 1); CP_COMMIT(); CP_WAIT(1); }
        else            { CP_WAIT(0); }
        __syncthreads();

        const uint32_t st = sbase + (c & 1) * STAGE_B;
        const uint32_t a_base = st;                       // Ah
        const uint32_t b_base = st + 2 * TILE_B;          // Bh

        // per-lane ldmatrix addresses (row part)
        const int arow = wm + (lane & 15);                // + i*16
        const int acol16 = (lane >> 4) * 16;              // 16B k-half select
        const int brow8 = wn + (lane & 7);                // + j*8
        const int bcol16 = ((lane >> 3) & 1) * 16;

#pragma unroll
        for (int ks = 0; ks < 2; ks++) {                  // two k16 steps per BK=32
            const int koff = ks * 32;                     // 16 fp16 = 32B
            uint32_t ahf[4][4], alf[4][4], bhf[4][2], blf[4][2];
#pragma unroll
            for (int i = 0; i < 4; i++) {
                uint32_t addr = a_base + (arow + i * 16) * ROW_B + acol16 + koff;
                ldsm_x4(ahf[i], addr);
                ldsm_x4(alf[i], addr + TILE_B);
            }
#pragma unroll
            for (int j = 0; j < 4; j++) {
                uint32_t addr = b_base + (brow8 + j * 8) * ROW_B + bcol16 + koff;
                ldsm_x2(bhf[j], addr);
                ldsm_x2(blf[j], addr + TILE_B);
            }
#pragma unroll
            for (int i = 0; i < 4; i++)
#pragma unroll
                for (int j = 0; j < 4; j++) {
                    mma16816(acc[i][j], ahf[i], bhf[j]);
                    mma16816(acc[i][j], ahf[i], blf[j]);
                    mma16816(acc[i][j], alf[i], bhf[j]);
                }
        }
        __syncthreads();
    }

    // ------- epilogue: c0,c1 -> (row, col..col+1); c2,c3 -> (row+8, ...)
    const int erow = brow + wm + (lane >> 2);
    const int ecol = bcol + wn + (lane & 3) * 2;
#pragma unroll
    for (int i = 0; i < 4; i++) {
#pragma unroll
        for (int j = 0; j < 4; j++) {
            float* p0 = C + (size_t)(erow + i * 16) * Nglob + ecol + j * 8;
            float* p1 = C + (size_t)(erow + i * 16 + 8) * Nglob + ecol + j * 8;
            *(float2*)p0 = make_float2(acc[i][j][0], acc[i][j][1]);
            *(float2*)p1 = make_float2(acc[i][j][2], acc[i][j][3]);
        }
    }
}

// ==========================================================================
// fp32 -> fp16 hi/lo split (row-major, same layout)
// ==========================================================================
__global__ __launch_bounds__(256) void convert_split(
    const float* __restrict__ x, __half* __restrict__ hi,
    __half* __restrict__ lo, int n4)
{
    int i = blockIdx.x * 256 + threadIdx.x;
    if (i >= n4) return;
    float4 v = ((const float4*)x)[i];
    float vals[4] = {v.x, v.y, v.z, v.w};
    __half hs[4], ls[4];
#pragma unroll
    for (int j = 0; j < 4; j++) {
        __half h = __float2half_rn(vals[j]);
        hs[j] = h;
        ls[j] = __float2half_rn(vals[j] - __half2float(h));
    }
    *(uint2*)(hi + i * 4) = *(uint2*)hs;
    *(uint2*)(lo + i * 4) = *(uint2*)ls;
}

// ==========================================================================
// W[K,N] fp32 -> W^T[N,K] fp16 hi/lo (32x32 tiled transpose)
// ==========================================================================
__global__ __launch_bounds__(256) void transpose_split(
    const float* __restrict__ W, __half* __restrict__ th,
    __half* __restrict__ tl, int K, int N)
{
    __shared__ float t[32][33];
    const int bx = blockIdx.x * 32;   // N offset
    const int by = blockIdx.y * 32;   // K offset
    const int tx = threadIdx.x;       // 0..31
    const int ty = threadIdx.y;       // 0..7
#pragma unroll
    for (int i = 0; i < 32; i += 8)
        t[ty + i][tx] = W[(size_t)(by + ty + i) * N + bx + tx];
    __syncthreads();
#pragma unroll
    for (int i = 0; i < 32; i += 8) {
        float v = t[tx][ty + i];
        __half h = __float2half_rn(v);
        size_t o = (size_t)(bx + ty + i) * K + by + tx;
        th[o] = h;
        tl[o] = __float2half_rn(v - __half2float(h));
    }
}

// ==========================================================================
// RoPE + split: g_qkv[s] -> g_q / g_k (NeoX rope) / g_v (copy), head-major.
// ==========================================================================
__global__ __launch_bounds__(256) void rope_split_kernel(const int* __restrict__ positions)
{
    const int s   = blockIdx.x;
    const int tid = threadIdx.x;
    __shared__ float cs[64], sn[64];

    if (tid < 64) {
        float inv_freq = powf(10000.0f, -((float)(2 * tid)) / 128.0f);
        float ang = (float)positions[s] * inv_freq;
        cs[tid] = cosf(ang);
        sn[tid] = sinf(ang);
    }
    __syncthreads();

    const float* row = g_qkv + (size_t)s * QKV_N;

    for (int idx = tid; idx < NH * 64; idx += 256) {
        int h = idx >> 6, d = idx & 63;
        float x1 = row[h * HD + d];
        float x2 = row[h * HD + d + 64];
        float* q = g_q + ((size_t)h * S_LEN + s) * HD;
        q[d]      = x1 * cs[d] - x2 * sn[d];
        q[d + 64] = x2 * cs[d] + x1 * sn[d];
    }
    for (int idx = tid; idx < NKV * 64; idx += 256) {
        int h = idx >> 6, d = idx & 63;
        const float* kr = row + QS;
        float x1 = kr[h * HD + d];
        float x2 = kr[h * HD + d + 64];
        float* k = g_k + ((size_t)h * S_LEN + s) * HD;
        k[d]      = x1 * cs[d] - x2 * sn[d];
        k[d + 64] = x2 * cs[d] + x1 * sn[d];
    }
    for (int idx = tid; idx < NKV * HD; idx += 256) {
        int h = idx >> 7, d = idx & 127;
        g_v[((size_t)h * S_LEN + s) * HD + d] = row[QS + KVS + h * HD + d];
    }
}

// ==========================================================================
// Flash attention, fp32, causal. Br=Bc=64, 256 threads.
// ==========================================================================
#define BR 64
#define BC 64
#define QK_STRIDE (BR + 4)
#define V_STRIDE  (HD + 4)
#define FLASH_SMEM_FLOATS (HD * QK_STRIDE + HD * QK_STRIDE \
                         + BC * V_STRIDE + BR * QK_STRIDE)

__global__ __launch_bounds__(256) void flash_attn_kernel()
{
    extern __shared__ float fsmem[];
    float* Qst = fsmem;
    float* Kst = Qst + HD * QK_STRIDE;
    float* Vs  = Kst + HD * QK_STRIDE;
    float* Ps  = Vs  + BC * V_STRIDE;

    const int qt  = blockIdx.x;
    const int h   = blockIdx.y;
    const int kvh = h >> 2;
    const int tid = threadIdx.x;
    const int ty  = tid >> 4;
    const int tx  = tid & 15;
    const int qbase = qt * BR;

    {
        const float* Qg = g_q + ((size_t)h * S_LEN + qbase) * HD;
        int r = tid & 63;
        int d0 = (tid >> 6) << 2;
#pragma unroll
        for (int i = 0; i < 8; i++) {
            int d = d0 + i * 16;
            float4 v = *(const float4*)(Qg + r * HD + d);
            Qst[(d + 0) * QK_STRIDE + r] = v.x;
            Qst[(d + 1) * QK_STRIDE + r] = v.y;
            Qst[(d + 2) * QK_STRIDE + r] = v.z;
            Qst[(d + 3) * QK_STRIDE + r] = v.w;
        }
    }

    float Ofrag[4][8];
    float m_i[4], l_i[4];
#pragma unroll
    for (int i = 0; i < 4; i++) {
        m_i[i] = -1e30f;
        l_i[i] = 0.0f;
#pragma unroll
        for (int j = 0; j < 8; j++) Ofrag[i][j] = 0.0f;
    }

    for (int jt = 0; jt <= qt; jt++) {
        const int kbase = jt * BC;
        {
            const float* Kg = g_k + ((size_t)kvh * S_LEN + kbase) * HD;
            const float* Vg = g_v + ((size_t)kvh * S_LEN + kbase) * HD;
            int c = tid & 63;
            int d0 = (tid >> 6) << 2;
#pragma unroll
            for (int i = 0; i < 8; i++) {
                int d = d0 + i * 16;
                float4 kv = *(const float4*)(Kg + c * HD + d);
                Kst[(d + 0) * QK_STRIDE + c] = kv.x;
                Kst[(d + 1) * QK_STRIDE + c] = kv.y;
                Kst[(d + 2) * QK_STRIDE + c] = kv.z;
                Kst[(d + 3) * QK_STRIDE + c] = kv.w;
                float4 vv = *(const float4*)(Vg + c * HD + d);
                *(float4*)&Vs[c * V_STRIDE + d] = vv;
            }
        }
        __syncthreads();

        float sfrag[4][4];
#pragma unroll
        for (int i = 0; i < 4; i++)
#pragma unroll
            for (int j = 0; j < 4; j++) sfrag[i][j] = 0.0f;

#pragma unroll 4
        for (int kk = 0; kk < HD; kk++) {
            float4 a = *(float4*)&Qst[kk * QK_STRIDE + ty * 4];
            float4 b = *(float4*)&Kst[kk * QK_STRIDE + tx * 4];
            float ar[4] = {a.x, a.y, a.z, a.w};
            float br[4] = {b.x, b.y, b.z, b.w};
#pragma unroll
            for (int i = 0; i < 4; i++)
#pragma unroll
                for (int j = 0; j < 4; j++)
                    sfrag[i][j] = fmaf(ar[i], br[j], sfrag[i][j]);
        }

        if (jt == qt) {
#pragma unroll
            for (int i = 0; i < 4; i++)
#pragma unroll
                for (int j = 0; j < 4; j++) {
                    float sv = sfrag[i][j] * SCALE;
                    sfrag[i][j] = (tx * 4 + j > ty * 4 + i) ? -1e30f : sv;
                }
        } else {
#pragma unroll
            for (int i = 0; i < 4; i++)
#pragma unroll
                for (int j = 0; j < 4; j++) sfrag[i][j] *= SCALE;
        }

#pragma unroll
        for (int i = 0; i < 4; i++) {
            float mloc = fmaxf(fmaxf(sfrag[i][0], sfrag[i][1]),
                               fmaxf(sfrag[i][2], sfrag[i][3]));
#pragma unroll
            for (int off = 8; off > 0; off >>= 1)
                mloc = fmaxf(mloc, __shfl_xor_sync(0xffffffffu, mloc, off, 16));

            float mnew  = fmaxf(m_i[i], mloc);
            float alpha = __expf(m_i[i] - mnew);
            float rsum = 0.0f;
            float p[4];
#pragma unroll
            for (int j = 0; j < 4; j++) {
                p[j] = __expf(sfrag[i][j] - mnew);
                rsum += p[j];
            }
            *(float4*)&Ps[(ty * 4 + i) * QK_STRIDE + tx * 4] =
                make_float4(p[0], p[1], p[2], p[3]);
#pragma unroll
            for (int off = 8; off > 0; off >>= 1)
                rsum += __shfl_xor_sync(0xffffffffu, rsum, off, 16);

            l_i[i] = l_i[i] * alpha + rsum;
            m_i[i] = mnew;
#pragma unroll
            for (int j = 0; j < 8; j++) Ofrag[i][j] *= alpha;
        }
        __syncthreads();

#pragma unroll 4
        for (int c = 0; c < BC; c++) {
            float4 v0 = *(float4*)&Vs[c * V_STRIDE + tx * 8];
            float4 v1 = *(float4*)&Vs[c * V_STRIDE + tx * 8 + 4];
            float vv[8] = {v0.x, v0.y, v0.z, v0.w, v1.x, v1.y, v1.z, v1.w};
#pragma unroll
            for (int i = 0; i < 4; i++) {
                float pv = Ps[(ty * 4 + i) * QK_STRIDE + c];
#pragma unroll
                for (int j = 0; j < 8; j++)
                    Ofrag[i][j] = fmaf(pv, vv[j], Ofrag[i][j]);
            }
        }
        __syncthreads();
    }

#pragma unroll
    for (int i = 0; i < 4; i++) {
        float inv_l = 1.0f / l_i[i];
        float* orow = g_attn + (size_t)(qbase + ty * 4 + i) * QS + h * HD + tx * 8;
        *(float4*)(orow) = make_float4(Ofrag[i][0] * inv_l, Ofrag[i][1] * inv_l,
                                       Ofrag[i][2] * inv_l, Ofrag[i][3] * inv_l);
        *(float4*)(orow + 4) = make_float4(Ofrag[i][4] * inv_l, Ofrag[i][5] * inv_l,
                                           Ofrag[i][6] * inv_l, Ofrag[i][7] * inv_l);
    }
}

// ==========================================================================
// launch
// ==========================================================================
extern "C" void kernel_launch(void* const* d_in, const int* in_sizes, int n_in,
                              void* d_out, int out_size)
{
    const int*   positions = (const int*)d_in[0];
    const float* hidden    = (const float*)d_in[1];
    const float* w_qkv     = (const float*)d_in[2];
    const float* w_o       = (const float*)d_in[3];
    float*       out       = (float*)d_out;

    void *p_qkv, *p_attn, *p_ah, *p_al, *p_wqh, *p_wql, *p_woh, *p_wol;
    cudaGetSymbolAddress(&p_qkv,  g_qkv);
    cudaGetSymbolAddress(&p_attn, g_attn);
    cudaGetSymbolAddress(&p_ah,   g_ah);
    cudaGetSymbolAddress(&p_al,   g_al);
    cudaGetSymbolAddress(&p_wqh,  g_wqh);
    cudaGetSymbolAddress(&p_wql,  g_wql);
    cudaGetSymbolAddress(&p_woh,  g_woh);
    cudaGetSymbolAddress(&p_wol,  g_wol);
    float* qkv  = (float*)p_qkv;
    float* attn = (float*)p_attn;
    __half* ah  = (__half*)p_ah;
    __half* al  = (__half*)p_al;
    __half* wqh = (__half*)p_wqh;
    __half* wql = (__half*)p_wql;
    __half* woh = (__half*)p_woh;
    __half* wol = (__half*)p_wol;

    const int flash_smem = FLASH_SMEM_FLOATS * (int)sizeof(float);
    cudaFuncSetAttribute(flash_attn_kernel,
                         cudaFuncAttributeMaxDynamicSharedMemorySize, flash_smem);
    cudaFuncSetAttribute(gemm_hmma_split,
                         cudaFuncAttributeMaxDynamicSharedMemorySize, GEMM_SMEM);

    // 1) operand prep for QKV GEMM
    {
        int n4 = (S_LEN * HID) / 4;
        convert_split<<<(n4 + 255) / 256, 256>>>(hidden, ah, al, n4);
        dim3 tg(QKV_N / 32, HID / 32);
        transpose_split<<<tg, dim3(32, 8)>>>(w_qkv, wqh, wql, HID, QKV_N);
    }
    // 2) QKV projection: [2048,4096] @ [4096,6144] via HMMA split-fp16
    {
        dim3 grid(QKV_N / 128, S_LEN / 128);
        gemm_hmma_split<<<grid, 256, GEMM_SMEM>>>(ah, al, wqh, wql, qkv, QKV_N, HID);
    }
    // 3) RoPE + head-major split
    rope_split_kernel<<<S_LEN, 256>>>(positions);
    // 4) causal GQA flash attention (fp32)
    {
        dim3 grid(S_LEN / BR, NH);
        flash_attn_kernel<<<grid, 256, flash_smem>>>();
    }
    // 5) operand prep for O GEMM
    {
        int n4 = (S_LEN * QS) / 4;
        convert_split<<<(n4 + 255) / 256, 256>>>(attn, ah, al, n4);
        dim3 tg(HID / 32, QS / 32);
        transpose_split<<<tg, dim3(32, 8)>>>(w_o, woh, wol, QS, HID);
    }
    // 6) output projection: [2048,4096] @ [4096,4096] via HMMA split-fp16
    {
        dim3 grid(HID / 128, S_LEN / 128);
        gemm_hmma_split<<<grid, 256, GEMM_SMEM>>>(ah, al, woh, wol, out, HID, QS);
    }
}

// round 9
// speedup vs baseline: 1.6020x; 1.6014x over previous
#include <cuda_runtime.h>
#include <cuda_fp16.h>
#include <cstdint>
#include <math.h>

// ---------------- problem constants ----------------
#define S_LEN 2048
#define HID   4096
#define NH    32
#define NKV   8
#define HD    128
#define QS    (NH * HD)          // 4096
#define KVS   (NKV * HD)         // 1024
#define QKV_N (QS + 2 * KVS)     // 6144
#define SCALE 0.08838834764831845f  // 128^-0.5
#define LOG2E 1.4426950408889634f

// ---------------- scratch (static device globals; no allocs) ----------------
__device__ float g_qkv[S_LEN * QKV_N];       // QKV projection output [S, 6144]

// fp16 split operands
__device__ __half g_ah[S_LEN * HID];         // activation hi [M,K] (hidden, then attn)
__device__ __half g_al[S_LEN * HID];         // activation lo
__device__ __half g_wqh[QKV_N * HID];        // w_qkv^T hi [N,K]
__device__ __half g_wql[QKV_N * HID];        // w_qkv^T lo
__device__ __half g_woh[HID * QS];           // w_o^T hi   [N,K]
__device__ __half g_wol[HID * QS];           // w_o^T lo

// fp16 split Q/K/V, head-major [h][s][d]
__device__ __half g_qh[NH * S_LEN * HD];
__device__ __half g_ql[NH * S_LEN * HD];
__device__ __half g_kh[NKV * S_LEN * HD];
__device__ __half g_kl[NKV * S_LEN * HD];
__device__ __half g_vh[NKV * S_LEN * HD];
__device__ __half g_vl[NKV * S_LEN * HD];

// ==========================================================================
// small PTX helpers
// ==========================================================================
__device__ __forceinline__ uint32_t smem_to_u32(const void* p) {
    uint32_t a;
    asm("{ .reg .u64 t; cvta.to.shared.u64 t, %1; cvt.u32.u64 %0, t; }"
        : "=r"(a) : "l"(p));
    return a;
}
__device__ __forceinline__ void cp_async16(uint32_t dst, const void* src) {
    asm volatile("cp.async.cg.shared.global [%0], [%1], 16;"
                 :: "r"(dst), "l"(src) : "memory");
}
#define CP_COMMIT() asm volatile("cp.async.commit_group;" ::: "memory")
#define CP_WAIT(n)  asm volatile("cp.async.wait_group %0;" :: "n"(n) : "memory")

__device__ __forceinline__ void ldsm_x4(uint32_t* r, uint32_t addr) {
    asm volatile("ldmatrix.sync.aligned.m8n8.x4.shared.b16 {%0,%1,%2,%3}, [%4];"
                 : "=r"(r[0]), "=r"(r[1]), "=r"(r[2]), "=r"(r[3]) : "r"(addr));
}
__device__ __forceinline__ void ldsm_x2(uint32_t* r, uint32_t addr) {
    asm volatile("ldmatrix.sync.aligned.m8n8.x2.shared.b16 {%0,%1}, [%2];"
                 : "=r"(r[0]), "=r"(r[1]) : "r"(addr));
}
__device__ __forceinline__ void ldsm_x2_trans(uint32_t* r, uint32_t addr) {
    asm volatile("ldmatrix.sync.aligned.m8n8.x2.trans.shared.b16 {%0,%1}, [%2];"
                 : "=r"(r[0]), "=r"(r[1]) : "r"(addr));
}
__device__ __forceinline__ void mma16816(float* c, const uint32_t* a, const uint32_t* b) {
    asm volatile("mma.sync.aligned.m16n8k16.row.col.f32.f16.f16.f32 "
                 "{%0,%1,%2,%3}, {%4,%5,%6,%7}, {%8,%9}, {%0,%1,%2,%3};"
                 : "+f"(c[0]), "+f"(c[1]), "+f"(c[2]), "+f"(c[3])
                 : "r"(a[0]), "r"(a[1]), "r"(a[2]), "r"(a[3]),
                   "r"(b[0]), "r"(b[1]));
}
__device__ __forceinline__ uint32_t packh2(float a, float b) {
    __half2 h = __floats2half2_rn(a, b);
    return *reinterpret_cast<uint32_t*>(&h);
}
// fast 2^t on FMA/ALU pipes (avoids MUFU bottleneck); rel err ~1e-7
__device__ __forceinline__ float fast_exp2(float t) {
    t = fmaxf(t, -126.0f);
    float z = t + 12582912.0f;                       // round-to-nearest-int trick
    int   n = __float_as_int(z) - 0x4B400000;
    float f = t - (z - 12582912.0f);                 // f in [-0.5, 0.5]
    float p = 1.5435339e-4f;
    p = fmaf(p, f, 1.3333558e-3f);
    p = fmaf(p, f, 9.6181291e-3f);
    p = fmaf(p, f, 5.5504109e-2f);
    p = fmaf(p, f, 2.4022651e-1f);
    p = fmaf(p, f, 6.9314718e-1f);
    p = fmaf(p, f, 1.0f);
    return __int_as_float(__float_as_int(p) + (n << 23));
}

// ==========================================================================
// split-fp16 HMMA GEMM: C[M,N] = (Ah+Al)[M,K] @ (Bh+Bl)[N,K]^T   (unchanged)
// ==========================================================================
#define ROW_B   80
#define TILE_B  (128 * ROW_B)
#define STAGE_B (4 * TILE_B)
#define GEMM_SMEM (2 * STAGE_B)

__global__ __launch_bounds__(256) void gemm_hmma_split(
    const __half* __restrict__ Ah, const __half* __restrict__ Al,
    const __half* __restrict__ Bh, const __half* __restrict__ Bl,
    float* __restrict__ C, int Nglob, int Kglob)
{
    extern __shared__ __align__(128) char smem[];
    const uint32_t sbase = smem_to_u32(smem);
    const int tid  = threadIdx.x;
    const int wid  = tid >> 5;
    const int lane = tid & 31;
    const int brow = blockIdx.y * 128;
    const int bcol = blockIdx.x * 128;
    const int NC   = Kglob / 32;

    const int wm = (wid >> 2) * 64;
    const int wn = (wid & 3) * 32;

    const __half* __restrict__ srcs[4] = { Ah, Al, Bh, Bl };

    float acc[4][4][4];
#pragma unroll
    for (int i = 0; i < 4; i++)
#pragma unroll
        for (int j = 0; j < 4; j++)
#pragma unroll
            for (int e = 0; e < 4; e++) acc[i][j][e] = 0.0f;

    auto load_stage = [&](int s, int c) {
        const int k0 = c * 32;
        const uint32_t stage = sbase + s * STAGE_B;
#pragma unroll
        for (int m = 0; m < 4; m++) {
            const int rowbase = (m < 2) ? brow : bcol;
            const __half* src = srcs[m];
#pragma unroll
            for (int t = 0; t < 2; t++) {
                int e  = tid + t * 256;
                int r  = e >> 2;
                int cc = e & 3;
                const void* g = src + (size_t)(rowbase + r) * Kglob + k0 + cc * 8;
                cp_async16(stage + m * TILE_B + r * ROW_B + cc * 16, g);
            }
        }
    };

    load_stage(0, 0);
    CP_COMMIT();

    for (int c = 0; c < NC; c++) {
        if (c + 1 < NC) { load_stage((c + 1) & 1, c + 1); CP_COMMIT(); CP_WAIT(1); }
        else            { CP_WAIT(0); }
        __syncthreads();

        const uint32_t st = sbase + (c & 1) * STAGE_B;
        const uint32_t a_base = st;
        const uint32_t b_base = st + 2 * TILE_B;

        const int arow = wm + (lane & 15);
        const int acol16 = (lane >> 4) * 16;
        const int brow8 = wn + (lane & 7);
        const int bcol16 = ((lane >> 3) & 1) * 16;

#pragma unroll
        for (int ks = 0; ks < 2; ks++) {
            const int koff = ks * 32;
            uint32_t ahf[4][4], alf[4][4], bhf[4][2], blf[4][2];
#pragma unroll
            for (int i = 0; i < 4; i++) {
                uint32_t addr = a_base + (arow + i * 16) * ROW_B + acol16 + koff;
                ldsm_x4(ahf[i], addr);
                ldsm_x4(alf[i], addr + TILE_B);
            }
#pragma unroll
            for (int j = 0; j < 4; j++) {
                uint32_t addr = b_base + (brow8 + j * 8) * ROW_B + bcol16 + koff;
                ldsm_x2(bhf[j], addr);
                ldsm_x2(blf[j], addr + TILE_B);
            }
#pragma unroll
            for (int i = 0; i < 4; i++)
#pragma unroll
                for (int j = 0; j < 4; j++) {
                    mma16816(acc[i][j], ahf[i], bhf[j]);
                    mma16816(acc[i][j], ahf[i], blf[j]);
                    mma16816(acc[i][j], alf[i], bhf[j]);
                }
        }
        __syncthreads();
    }

    const int erow = brow + wm + (lane >> 2);
    const int ecol = bcol + wn + (lane & 3) * 2;
#pragma unroll
    for (int i = 0; i < 4; i++) {
#pragma unroll
        for (int j = 0; j < 4; j++) {
            float* p0 = C + (size_t)(erow + i * 16) * Nglob + ecol + j * 8;
            float* p1 = C + (size_t)(erow + i * 16 + 8) * Nglob + ecol + j * 8;
            *(float2*)p0 = make_float2(acc[i][j][0], acc[i][j][1]);
            *(float2*)p1 = make_float2(acc[i][j][2], acc[i][j][3]);
        }
    }
}

// ==========================================================================
// fp32 -> fp16 hi/lo split
// ==========================================================================
__global__ __launch_bounds__(256) void convert_split(
    const float* __restrict__ x, __half* __restrict__ hi,
    __half* __restrict__ lo, int n4)
{
    int i = blockIdx.x * 256 + threadIdx.x;
    if (i >= n4) return;
    float4 v = ((const float4*)x)[i];
    float vals[4] = {v.x, v.y, v.z, v.w};
    __half hs[4], ls[4];
#pragma unroll
    for (int j = 0; j < 4; j++) {
        __half h = __float2half_rn(vals[j]);
        hs[j] = h;
        ls[j] = __float2half_rn(vals[j] - __half2float(h));
    }
    *(uint2*)(hi + i * 4) = *(uint2*)hs;
    *(uint2*)(lo + i * 4) = *(uint2*)ls;
}

// ==========================================================================
// W[K,N] fp32 -> W^T[N,K] fp16 hi/lo
// ==========================================================================
__global__ __launch_bounds__(256) void transpose_split(
    const float* __restrict__ W, __half* __restrict__ th,
    __half* __restrict__ tl, int K, int N)
{
    __shared__ float t[32][33];
    const int bx = blockIdx.x * 32;
    const int by = blockIdx.y * 32;
    const int tx = threadIdx.x;
    const int ty = threadIdx.y;
#pragma unroll
    for (int i = 0; i < 32; i += 8)
        t[ty + i][tx] = W[(size_t)(by + ty + i) * N + bx + tx];
    __syncthreads();
#pragma unroll
    for (int i = 0; i < 32; i += 8) {
        float v = t[tx][ty + i];
        __half h = __float2half_rn(v);
        size_t o = (size_t)(bx + ty + i) * K + by + tx;
        th[o] = h;
        tl[o] = __float2half_rn(v - __half2float(h));
    }
}

// ==========================================================================
// RoPE + split -> fp16 hi/lo Q/K/V, head-major
// ==========================================================================
__global__ __launch_bounds__(256) void rope_split_kernel(const int* __restrict__ positions)
{
    const int s   = blockIdx.x;
    const int tid = threadIdx.x;
    __shared__ float cs[64], sn[64];

    if (tid < 64) {
        float inv_freq = powf(10000.0f, -((float)(2 * tid)) / 128.0f);
        float ang = (float)positions[s] * inv_freq;
        cs[tid] = cosf(ang);
        sn[tid] = sinf(ang);
    }
    __syncthreads();

    const float* row = g_qkv + (size_t)s * QKV_N;

    for (int idx = tid; idx < NH * 64; idx += 256) {
        int h = idx >> 6, d = idx & 63;
        float x1 = row[h * HD + d];
        float x2 = row[h * HD + d + 64];
        float a = x1 * cs[d] - x2 * sn[d];
        float b = x2 * cs[d] + x1 * sn[d];
        size_t o = ((size_t)h * S_LEN + s) * HD;
        __half ha = __float2half_rn(a), hb = __float2half_rn(b);
        g_qh[o + d]      = ha;
        g_qh[o + d + 64] = hb;
        g_ql[o + d]      = __float2half_rn(a - __half2float(ha));
        g_ql[o + d + 64] = __float2half_rn(b - __half2float(hb));
    }
    for (int idx = tid; idx < NKV * 64; idx += 256) {
        int h = idx >> 6, d = idx & 63;
        const float* kr = row + QS;
        float x1 = kr[h * HD + d];
        float x2 = kr[h * HD + d + 64];
        float a = x1 * cs[d] - x2 * sn[d];
        float b = x2 * cs[d] + x1 * sn[d];
        size_t o = ((size_t)h * S_LEN + s) * HD;
        __half ha = __float2half_rn(a), hb = __float2half_rn(b);
        g_kh[o + d]      = ha;
        g_kh[o + d + 64] = hb;
        g_kl[o + d]      = __float2half_rn(a - __half2float(ha));
        g_kl[o + d + 64] = __float2half_rn(b - __half2float(hb));
    }
    for (int idx = tid; idx < NKV * HD; idx += 256) {
        int h = idx >> 7, d = idx & 127;
        float v = row[QS + KVS + h * HD + d];
        size_t o = ((size_t)h * S_LEN + s) * HD + d;
        __half hv = __float2half_rn(v);
        g_vh[o] = hv;
        g_vl[o] = __float2half_rn(v - __half2float(hv));
    }
}

// ==========================================================================
// HMMA flash attention: BR=128, BC=64, 8 warps (each 16 q rows), causal GQA.
// QK^T and P@V via split-fp16 mma.sync; softmax on FMA/ALU via fast_exp2.
// Output written as fp16 hi/lo splits directly into g_ah/g_al for the O GEMM.
// ==========================================================================
#define FROW 272                          // smem row stride bytes (128 fp16 + pad)
#define FQ_H 0
#define FQ_L (128 * FROW)                 // 34816
#define FSTAGE0 (2 * 128 * FROW)          // 69632
#define FSTAGE_B (4 * 64 * FROW)          // 69632 (Kh, Kl, Vh, Vl)
#define FK_H 0
#define FK_L (64 * FROW)
#define FV_H (2 * 64 * FROW)
#define FV_L (3 * 64 * FROW)
#define FLASH_SMEM (FSTAGE0 + 2 * FSTAGE_B)   // 208896

__global__ __launch_bounds__(256, 1) void flash_hmma_kernel()
{
    extern __shared__ __align__(128) char smem[];
    const uint32_t sbase = smem_to_u32(smem);
    const int tid  = threadIdx.x;
    const int wid  = tid >> 5;
    const int lane = tid & 31;
    const int qt   = blockIdx.x;          // 0..15
    const int h    = blockIdx.y;          // 0..31
    const int kvh  = h >> 2;
    const int qbase = qt * 128;
    const int wr   = wid * 16;            // warp's q-row offset in tile
    const int jlast = 2 * qt + 1;

    const __half* Qhg = g_qh + ((size_t)h * S_LEN + qbase) * HD;
    const __half* Qlg = g_ql + ((size_t)h * S_LEN + qbase) * HD;
    const __half* Khg = g_kh + (size_t)kvh * S_LEN * HD;
    const __half* Klg = g_kl + (size_t)kvh * S_LEN * HD;
    const __half* Vhg = g_vh + (size_t)kvh * S_LEN * HD;
    const __half* Vlg = g_vl + (size_t)kvh * S_LEN * HD;

    // ---- load Q tiles (hi, lo): 2 x 2048 chunks, 8 per thread per tile
    {
#pragma unroll
        for (int t = 0; t < 8; t++) {
            int e = tid + t * 256;            // 0..2047
            int r = e >> 4, c = e & 15;
            cp_async16(sbase + FQ_H + r * FROW + c * 16, Qhg + r * HD + c * 8);
        }
#pragma unroll
        for (int t = 0; t < 8; t++) {
            int e = tid + t * 256;
            int r = e >> 4, c = e & 15;
            cp_async16(sbase + FQ_L + r * FROW + c * 16, Qlg + r * HD + c * 8);
        }
    }

    // ---- K/V stage loader: 4 tiles x 1024 chunks = 16 per thread
    auto load_stage = [&](int s, int jt) {
        const uint32_t stage = sbase + FSTAGE0 + s * FSTAGE_B;
        const int kbase = jt * 64;
        const __half* gs[4] = { Khg, Klg, Vhg, Vlg };
        const uint32_t off[4] = { FK_H, FK_L, FV_H, FV_L };
#pragma unroll
        for (int m = 0; m < 4; m++) {
#pragma unroll
            for (int t = 0; t < 4; t++) {
                int e = tid + t * 256;        // 0..1023
                int r = e >> 4, c = e & 15;
                cp_async16(stage + off[m] + r * FROW + c * 16,
                           gs[m] + (size_t)(kbase + r) * HD + c * 8);
            }
        }
    };

    load_stage(0, 0);
    CP_COMMIT();

    float oacc[16][4];
    float m0 = -1e30f, m1 = -1e30f, l0 = 0.0f, l1 = 0.0f;
#pragma unroll
    for (int nt = 0; nt < 16; nt++)
#pragma unroll
        for (int e = 0; e < 4; e++) oacc[nt][e] = 0.0f;

    const int rq = lane >> 2;                 // 0..7
    const int cq = (lane & 3) * 2;            // 0,2,4,6
    const float s2scale = SCALE * LOG2E;

    for (int jt = 0; jt <= jlast; jt++) {
        if (jt + 1 <= jlast) { load_stage((jt + 1) & 1, jt + 1); CP_COMMIT(); CP_WAIT(1); }
        else                 { CP_WAIT(0); }
        __syncthreads();

        // warp-uniform skip: this warp's rows all above the diagonal for this tile
        const bool active = (jt * 64 <= qbase + wr + 15);
        if (active) {
            const uint32_t stage = sbase + FSTAGE0 + (jt & 1) * FSTAGE_B;

            // ---- S = Q @ K^T (split: 3 mma)
            float sacc[8][4];
#pragma unroll
            for (int nt = 0; nt < 8; nt++)
#pragma unroll
                for (int e = 0; e < 4; e++) sacc[nt][e] = 0.0f;

            const int arow = wr + (lane & 15);
            const int acol16 = (lane >> 4) * 16;
            const int bl8 = lane & 7;
            const int bsel = ((lane >> 3) & 1) * 16;

#pragma unroll
            for (int kk = 0; kk < 8; kk++) {
                uint32_t ah[4], al[4];
                uint32_t qaddr = sbase + FQ_H + arow * FROW + kk * 32 + acol16;
                ldsm_x4(ah, qaddr);
                ldsm_x4(al, qaddr + FQ_L);
#pragma unroll
                for (int nt = 0; nt < 8; nt++) {
                    uint32_t bh[2], bl[2];
                    uint32_t kaddr = stage + FK_H + (nt * 8 + bl8) * FROW + kk * 32 + bsel;
                    ldsm_x2(bh, kaddr);
                    ldsm_x2(bl, kaddr + (FK_L - FK_H));
                    mma16816(sacc[nt], ah, bh);
                    mma16816(sacc[nt], ah, bl);
                    mma16816(sacc[nt], al, bh);
                }
            }

            // ---- scale to base-2, causal mask (diagonal tiles only)
            const int row0 = qbase + wr + rq;
            if (jt >= 2 * qt) {
#pragma unroll
                for (int nt = 0; nt < 8; nt++) {
                    int col = jt * 64 + nt * 8 + cq;
#pragma unroll
                    for (int e = 0; e < 4; e++) {
                        int cc = col + (e & 1);
                        int rr = row0 + ((e >> 1) ? 8 : 0);
                        float sv = sacc[nt][e] * s2scale;
                        sacc[nt][e] = (cc > rr) ? -1e30f : sv;
                    }
                }
            } else {
#pragma unroll
                for (int nt = 0; nt < 8; nt++)
#pragma unroll
                    for (int e = 0; e < 4; e++) sacc[nt][e] *= s2scale;
            }

            // ---- online softmax (base-2), rows r0 = rq, r1 = rq+8
            float mx0 = -1e30f, mx1 = -1e30f;
#pragma unroll
            for (int nt = 0; nt < 8; nt++) {
                mx0 = fmaxf(mx0, fmaxf(sacc[nt][0], sacc[nt][1]));
                mx1 = fmaxf(mx1, fmaxf(sacc[nt][2], sacc[nt][3]));
            }
#pragma unroll
            for (int off = 1; off <= 2; off <<= 1) {
                mx0 = fmaxf(mx0, __shfl_xor_sync(0xffffffffu, mx0, off));
                mx1 = fmaxf(mx1, __shfl_xor_sync(0xffffffffu, mx1, off));
            }
            float mn0 = fmaxf(m0, mx0), mn1 = fmaxf(m1, mx1);
            float alpha0 = fast_exp2(m0 - mn0), alpha1 = fast_exp2(m1 - mn1);

            float rs0 = 0.0f, rs1 = 0.0f;
#pragma unroll
            for (int nt = 0; nt < 8; nt++) {
                sacc[nt][0] = fast_exp2(sacc[nt][0] - mn0);
                sacc[nt][1] = fast_exp2(sacc[nt][1] - mn0);
                sacc[nt][2] = fast_exp2(sacc[nt][2] - mn1);
                sacc[nt][3] = fast_exp2(sacc[nt][3] - mn1);
                rs0 += sacc[nt][0] + sacc[nt][1];
                rs1 += sacc[nt][2] + sacc[nt][3];
            }
#pragma unroll
            for (int off = 1; off <= 2; off <<= 1) {
                rs0 += __shfl_xor_sync(0xffffffffu, rs0, off);
                rs1 += __shfl_xor_sync(0xffffffffu, rs1, off);
            }
            l0 = l0 * alpha0 + rs0;
            l1 = l1 * alpha1 + rs1;
            m0 = mn0; m1 = mn1;

#pragma unroll
            for (int nt = 0; nt < 16; nt++) {
                oacc[nt][0] *= alpha0; oacc[nt][1] *= alpha0;
                oacc[nt][2] *= alpha1; oacc[nt][3] *= alpha1;
            }

            // ---- P fragments (hi/lo) from accumulator layout (no smem round trip)
            uint32_t ph[4][4], pl[4][4];
#pragma unroll
            for (int kt = 0; kt < 4; kt++) {
                const float* pA = sacc[2 * kt];
                const float* pB = sacc[2 * kt + 1];
                uint32_t h0 = packh2(pA[0], pA[1]);
                uint32_t h1 = packh2(pA[2], pA[3]);
                uint32_t h2 = packh2(pB[0], pB[1]);
                uint32_t h3 = packh2(pB[2], pB[3]);
                ph[kt][0] = h0; ph[kt][1] = h1; ph[kt][2] = h2; ph[kt][3] = h3;
                __half2 hh0 = *reinterpret_cast<__half2*>(&h0);
                __half2 hh1 = *reinterpret_cast<__half2*>(&h1);
                __half2 hh2 = *reinterpret_cast<__half2*>(&h2);
                __half2 hh3 = *reinterpret_cast<__half2*>(&h3);
                pl[kt][0] = packh2(pA[0] - __low2float(hh0), pA[1] - __high2float(hh0));
                pl[kt][1] = packh2(pA[2] - __low2float(hh1), pA[3] - __high2float(hh1));
                pl[kt][2] = packh2(pB[0] - __low2float(hh2), pB[1] - __high2float(hh2));
                pl[kt][3] = packh2(pB[2] - __low2float(hh3), pB[3] - __high2float(hh3));
            }

            // ---- O += P @ V (split: Ph*Vh + Ph*Vl + Pl*Vh)
            const int vl16 = lane & 15;
#pragma unroll
            for (int kt = 0; kt < 4; kt++) {
#pragma unroll
                for (int nt = 0; nt < 16; nt++) {
                    uint32_t vh[2], vl[2];
                    uint32_t vaddr = stage + FV_H + (kt * 16 + vl16) * FROW + nt * 16;
                    ldsm_x2_trans(vh, vaddr);
                    ldsm_x2_trans(vl, vaddr + (FV_L - FV_H));
                    mma16816(oacc[nt], ph[kt], vh);
                    mma16816(oacc[nt], ph[kt], vl);
                    mma16816(oacc[nt], pl[kt], vh);
                }
            }
        }
        __syncthreads();
    }

    // ---- epilogue: normalize, split to fp16 hi/lo, write into O-GEMM A buffers
    const float inv0 = 1.0f / l0;
    const float inv1 = 1.0f / l1;
    const int row0 = qbase + wr + (lane >> 2);
    const int colb = h * HD + (lane & 3) * 2;
#pragma unroll
    for (int nt = 0; nt < 16; nt++) {
        int col = colb + nt * 8;
        {
            float a = oacc[nt][0] * inv0, b = oacc[nt][1] * inv0;
            uint32_t hh = packh2(a, b);
            __half2 h2v = *reinterpret_cast<__half2*>(&hh);
            uint32_t ll = packh2(a - __low2float(h2v), b - __high2float(h2v));
            *(uint32_t*)(g_ah + (size_t)row0 * HID + col) = hh;
            *(uint32_t*)(g_al + (size_t)row0 * HID + col) = ll;
        }
        {
            float a = oacc[nt][2] * inv1, b = oacc[nt][3] * inv1;
            uint32_t hh = packh2(a, b);
            __half2 h2v = *reinterpret_cast<__half2*>(&hh);
            uint32_t ll = packh2(a - __low2float(h2v), b - __high2float(h2v));
            *(uint32_t*)(g_ah + (size_t)(row0 + 8) * HID + col) = hh;
            *(uint32_t*)(g_al + (size_t)(row0 + 8) * HID + col) = ll;
        }
    }
}

// ==========================================================================
// launch
// ==========================================================================
extern "C" void kernel_launch(void* const* d_in, const int* in_sizes, int n_in,
                              void* d_out, int out_size)
{
    const int*   positions = (const int*)d_in[0];
    const float* hidden    = (const float*)d_in[1];
    const float* w_qkv     = (const float*)d_in[2];
    const float* w_o       = (const float*)d_in[3];
    float*       out       = (float*)d_out;

    void *p_qkv, *p_ah, *p_al, *p_wqh, *p_wql, *p_woh, *p_wol;
    cudaGetSymbolAddress(&p_qkv,  g_qkv);
    cudaGetSymbolAddress(&p_ah,   g_ah);
    cudaGetSymbolAddress(&p_al,   g_al);
    cudaGetSymbolAddress(&p_wqh,  g_wqh);
    cudaGetSymbolAddress(&p_wql,  g_wql);
    cudaGetSymbolAddress(&p_woh,  g_woh);
    cudaGetSymbolAddress(&p_wol,  g_wol);
    float* qkv  = (float*)p_qkv;
    __half* ah  = (__half*)p_ah;
    __half* al  = (__half*)p_al;
    __half* wqh = (__half*)p_wqh;
    __half* wql = (__half*)p_wql;
    __half* woh = (__half*)p_woh;
    __half* wol = (__half*)p_wol;

    cudaFuncSetAttribute(gemm_hmma_split,
                         cudaFuncAttributeMaxDynamicSharedMemorySize, GEMM_SMEM);
    cudaFuncSetAttribute(flash_hmma_kernel,
                         cudaFuncAttributeMaxDynamicSharedMemorySize, FLASH_SMEM);

    // 1) operand prep for QKV GEMM
    {
        int n4 = (S_LEN * HID) / 4;
        convert_split<<<(n4 + 255) / 256, 256>>>(hidden, ah, al, n4);
        dim3 tg(QKV_N / 32, HID / 32);
        transpose_split<<<tg, dim3(32, 8)>>>(w_qkv, wqh, wql, HID, QKV_N);
    }
    // 2) QKV projection
    {
        dim3 grid(QKV_N / 128, S_LEN / 128);
        gemm_hmma_split<<<grid, 256, GEMM_SMEM>>>(ah, al, wqh, wql, qkv, QKV_N, HID);
    }
    // 3) RoPE + fp16 hi/lo split (head-major)
    rope_split_kernel<<<S_LEN, 256>>>(positions);
    // 4) HMMA flash attention -> writes attn hi/lo into g_ah/g_al
    {
        dim3 grid(S_LEN / 128, NH);
        flash_hmma_kernel<<<grid, 256, FLASH_SMEM>>>();
    }
    // 5) O-GEMM operand prep (weights only; attn splits already written)
    {
        dim3 tg(HID / 32, QS / 32);
        transpose_split<<<tg, dim3(32, 8)>>>(w_o, woh, wol, QS, HID);
    }
    // 6) output projection
    {
        dim3 grid(HID / 128, S_LEN / 128);
        gemm_hmma_split<<<grid, 256, GEMM_SMEM>>>(ah, al, woh, wol, out, HID, QS);
    }
}